// round 11
// baseline (speedup 1.0000x reference)
#include <cuda_runtime.h>
#include <math.h>

#define NCLS 1000
#define BATCH 1024
#define BETA 0.7f
#define LAMBDA1 3.0f
#define CLIP_EPS 1e-4f
#define THREADS 256
#define PER_THREAD 4        // 256*4 = 1024 >= 1000

#define ROW_BLOCKS  BATCH       // blocks 0..1023 do a loss row, then copy
#define TOT_BLOCKS  1184        // 148 SMs * 8 CTAs -> exactly one wave
#define TOT_THREADS ((long long)TOT_BLOCKS * THREADS)

// per-row loss partials (ce + LAMBDA1*elr), unique slot per row -> no atomics
__device__ float        g_part[BATCH];
__device__ unsigned int g_count;   // zero at load; last block resets to 0

// block-wide reduction (sum if SUM=true else max), result broadcast
template <bool SUM>
__device__ __forceinline__ float block_reduce(float val, float* sred) {
    #pragma unroll
    for (int o = 16; o > 0; o >>= 1) {
        float other = __shfl_xor_sync(0xFFFFFFFFu, val, o);
        val = SUM ? (val + other) : fmaxf(val, other);
    }
    int lane = threadIdx.x & 31;
    int warp = threadIdx.x >> 5;
    if (lane == 0) sred[warp] = val;
    __syncthreads();
    if (warp == 0) {
        val = (lane < (THREADS / 32)) ? sred[lane] : (SUM ? 0.0f : -INFINITY);
        #pragma unroll
        for (int o = 4; o > 0; o >>= 1) {
            float other = __shfl_xor_sync(0xFFFFFFFFu, val, o);
            val = SUM ? (val + other) : fmaxf(val, other);
        }
        if (lane == 0) sred[0] = val;
    }
    __syncthreads();
    float r = sred[0];
    __syncthreads();
    return r;
}

// copy one 64B chunk (16 floats): 16 scalar loads (src 4B-aligned),
// 4 x STG.128 (dst 16B-aligned). Loads are front-batched -> MLP 16.
__device__ __forceinline__ void copy_chunk(const float* __restrict__ s,
                                           float* __restrict__ d) {
    float v[16];
    #pragma unroll
    for (int j = 0; j < 16; j++) v[j] = __ldcs(s + j);
    #pragma unroll
    for (int q = 0; q < 4; q++) {
        float4 val = make_float4(v[4*q], v[4*q+1], v[4*q+2], v[4*q+3]);
        __stcs((float4*)d + q, val);
    }
}

__global__ __launch_bounds__(THREADS) void elr_fused_kernel(
    const float* __restrict__ logits,   // [BATCH, NCLS]
    const float* __restrict__ target,   // [NUM_EXAMP, NCLS]
    const int*   __restrict__ label,    // [BATCH]
    const int*   __restrict__ index_p,  // [1]
    float*       __restrict__ out,      // out[0]=loss, out+1 = new_target
    long long n,                        // target element count
    int write_target)
{
    __shared__ float sred[32];
    __shared__ bool  s_last;

    const int tid = threadIdx.x;
    const long long lo = (long long)index_p[0] * BATCH * NCLS;  // updated range
    const long long hi = lo + (long long)BATCH * NCLS;
    float* __restrict__ dst = out + 1;

    if (blockIdx.x < ROW_BLOCKS) {
        // ----------------- loss row work -----------------
        const int row = blockIdx.x;
        const float* x = logits + (size_t)row * NCLS;

        float v[PER_THREAD];
        #pragma unroll
        for (int k = 0; k < PER_THREAD; k++) {
            int i = tid + k * THREADS;
            v[k] = (i < NCLS) ? x[i] : -INFINITY;
        }

        // 1) max
        float m = v[0];
        #pragma unroll
        for (int k = 1; k < PER_THREAD; k++) m = fmaxf(m, v[k]);
        m = block_reduce<false>(m, sred);

        // 2) sum of exp
        float e[PER_THREAD];
        float lsum = 0.0f;
        #pragma unroll
        for (int k = 0; k < PER_THREAD; k++) {
            int i = tid + k * THREADS;
            e[k] = (i < NCLS) ? expf(v[k] - m) : 0.0f;
            lsum += e[k];
        }
        const float sumexp = block_reduce<true>(lsum, sred);
        const float inv_sumexp = 1.0f / sumexp;

        // 3) y_pred = clip(softmax) and its sum
        float yp[PER_THREAD];
        float lclip = 0.0f;
        #pragma unroll
        for (int k = 0; k < PER_THREAD; k++) {
            int i = tid + k * THREADS;
            if (i < NCLS) {
                float p = e[k] * inv_sumexp;
                p = fminf(fmaxf(p, CLIP_EPS), 1.0f - CLIP_EPS);
                yp[k] = p;
                lclip += p;
            } else {
                yp[k] = 0.0f;
            }
        }
        const float sclip = block_reduce<true>(lclip, sred);
        const float inv_sclip = 1.0f / sclip;

        // 4) EMA row update + dot(new_row, y_pred)
        const float* trow = target + lo + (size_t)row * NCLS;
        float* drow = dst + lo + (size_t)row * NCLS;

        float ldot = 0.0f;
        #pragma unroll
        for (int k = 0; k < PER_THREAD; k++) {
            int i = tid + k * THREADS;
            if (i < NCLS) {
                float yn = yp[k] * inv_sclip;
                float nr = BETA * trow[i] + (1.0f - BETA) * yn;
                if (write_target) drow[i] = nr;
                ldot += nr * yp[k];
            }
        }
        const float dot = block_reduce<true>(ldot, sred);

        // 5) per-row partial: ce + LAMBDA1 * elr
        if (tid == 0) {
            const int lab = label[row];
            const float ce  = -(x[lab] - m - logf(sumexp));
            const float elr = logf(1.0f - dot);
            g_part[row] = ce + LAMBDA1 * elr;
        }
    }

    if (write_target) {
        // ------------- branch-free shifted bulk copy, skipping [lo,hi) -------------
        // chunk c covers elements [3+16c, 3+16c+16); dst+3 is 16B aligned.
        const long long gid     = (long long)blockIdx.x * THREADS + tid;
        const long long nchunks = (n - 3) >> 4;

        // cA = number of chunks fully before lo; cB = first chunk fully after hi
        long long cA = (lo >= 19) ? (((lo - 19) >> 4) + 1) : 0;
        if (cA > nchunks) cA = nchunks;
        long long cB = (hi > 3) ? ((hi - 3 + 15) >> 4) : 0;
        if (cB > nchunks) cB = nchunks;
        if (cB < cA) cB = cA;

        // loop 1: chunks fully before the updated range
        for (long long c = gid; c < cA; c += TOT_THREADS)
            copy_chunk(target + 3 + (c << 4), dst + 3 + (c << 4));

        // loop 2: chunks fully after the updated range
        for (long long c = cB + gid; c < nchunks; c += TOT_THREADS)
            copy_chunk(target + 3 + (c << 4), dst + 3 + (c << 4));

        // scalar fixups (head, partial chunks at lo/hi, tail): <= ~48 elements
        if (blockIdx.x == ROW_BLOCKS) {
            // head [0,3)
            for (long long i = tid; i < 3 && i < n; i += THREADS)
                if (i < lo || i >= hi) dst[i] = __ldcs(target + i);
            // partial-left [3+16*cA, lo)
            {
                long long s0 = 3 + (cA << 4);
                for (long long i = s0 + tid; i < lo && i < n; i += THREADS)
                    dst[i] = __ldcs(target + i);
            }
            // partial-right [hi, 3+16*cB)
            {
                long long e1 = 3 + (cB << 4);
                if (e1 > n) e1 = n;
                for (long long i = hi + tid; i < e1; i += THREADS)
                    dst[i] = __ldcs(target + i);
            }
            // tail [3+16*nchunks, n)
            {
                long long t0 = 3 + (nchunks << 4);
                for (long long i = t0 + tid; i < n; i += THREADS)
                    if (i < lo || i >= hi) dst[i] = __ldcs(target + i);
            }
        }
    }

    // ----------------- completion: last block reduces partials -----------------
    __threadfence();
    __syncthreads();
    if (tid == 0) {
        unsigned int t = atomicAdd(&g_count, 1u);
        s_last = (t == TOT_BLOCKS - 1);
    }
    __syncthreads();

    if (s_last) {
        __threadfence();
        float lsum = 0.0f;
        #pragma unroll
        for (int k = 0; k < BATCH / THREADS; k++) {
            lsum += g_part[tid + k * THREADS];
        }
        const float total = block_reduce<true>(lsum, sred);
        if (tid == 0) {
            out[0] = total * (1.0f / BATCH);
            g_count = 0;   // restore invariant for graph replay
        }
    }
}

extern "C" void kernel_launch(void* const* d_in, const int* in_sizes, int n_in,
                              void* d_out, int out_size) {
    const float* logits = (const float*)d_in[0];
    const float* target = (const float*)d_in[1];
    const int*   label  = (const int*)d_in[2];
    const int*   index  = (const int*)d_in[3];
    float* out = (float*)d_out;

    const long long tgt_elems = (long long)in_sizes[1];   // 200,000,000
    const int write_target = (out_size > 1) ? 1 : 0;

    elr_fused_kernel<<<TOT_BLOCKS, THREADS>>>(logits, target, label, index,
                                              out, tgt_elems, write_target);
}